// round 14
// baseline (speedup 1.0000x reference)
#include <cuda_runtime.h>
#include <cuda_bf16.h>
#include <cstdint>

#define TT 128
#define BB 256
#define FF 76
#define HH 64
#define GG 192   // 3*H
#define NHEAD 4
#define DFF 256
#define AH 8

// ---------------- scratch (device globals; no runtime allocation) ----------------
__device__ float g_hs[(size_t)FF * BB * TT * HH];   // [F][B][T][H]
__device__ float g_emb[(size_t)BB * FF * HH];       // [B][F][H]

// ---------------- helpers ----------------
__device__ __forceinline__ float sigmoidf_(float x) {
    return __fdividef(1.0f, 1.0f + __expf(-x));
}
__device__ __forceinline__ float tanh_ap(float x) {
    float y;
    asm("tanh.approx.f32 %0, %1;" : "=f"(y) : "f"(x));
    return y;
}
__device__ __forceinline__ unsigned long long ffma2(unsigned long long a,
                                                    unsigned long long b,
                                                    unsigned long long c) {
    unsigned long long d;
    asm("fma.rn.f32x2 %0, %1, %2, %3;" : "=l"(d) : "l"(a), "l"(b), "l"(c));
    return d;
}
__device__ __forceinline__ unsigned long long dup2(float v) {
    unsigned long long d;
    asm("mov.b64 %0, {%1, %1};" : "=l"(d) : "f"(v));
    return d;
}
__device__ __forceinline__ float2 u2f(unsigned long long u) {
    return *(float2*)&u;
}

// =====================================================================
// Kernel A: fused per-feature GRU scan + per-(f,b) time attention.
// (unchanged from R13 — GRU at FFMA2 floor)
// =====================================================================
#define WT_S 194          // wT row stride (floats)
#define HT_S 34           // h row stride (floats, even)
#define XCH 32            // t-chunk
#define SMEM_A_FLOATS (64 * WT_S + 2 * 64 * HT_S + GG + 128 + 64 + 64 + XCH * 32)

__global__ void __launch_bounds__(128, 3) gru_attn_kernel(
    const float* __restrict__ x,        // (T,B,F)
    const float* __restrict__ w_ih,     // (F,3H)
    const float* __restrict__ w_hh,     // (F,3H,H)
    const float* __restrict__ b_ih,     // (F,3H)
    const float* __restrict__ b_hh,     // (F,3H)
    const float* __restrict__ att_Wt,   // (F,H,AH)
    const float* __restrict__ att_Wx,   // (F,H,AH)
    const float* __restrict__ att_rate) // (F,)
{
    extern __shared__ float sm[];
    float* wT   = sm;                          // [64][194]
    float* hbuf = wT + 64 * WT_S;              // 2 x [64][34]
    float* swih = hbuf + 2 * 64 * HT_S;        // 192 (*0.5 for first 128)
    float* sbrz = swih + GG;                   // 128
    float* sbin = sbrz + 128;                  // 64
    float* sbhn = sbin + 64;                   // 64
    float* sxc  = sbhn + 64;                   // XCH*32

    const int f  = blockIdx.y;
    const int b0 = blockIdx.x * 32;
    const int tid = threadIdx.x;
    const int tx = tid & 31, ty = tid >> 5;
    const int j0 = 2 * tx;
    const int bloc = 8 * ty;

    const float* whf = w_hh + (size_t)f * GG * HH;
    for (int idx = tid; idx < GG * HH; idx += 128) {
        const int g = idx >> 6, k = idx & 63;
        const float s = (g < 128) ? 0.5f : 1.0f;
        wT[k * WT_S + g] = whf[idx] * s;
    }
    for (int idx = tid; idx < GG; idx += 128) {
        const float s = (idx < 128) ? 0.5f : 1.0f;
        swih[idx] = w_ih[(size_t)f * GG + idx] * s;
    }
    if (tid < 128) sbrz[tid] = 0.5f * (b_ih[(size_t)f * GG + tid] + b_hh[(size_t)f * GG + tid]);
    if (tid < 64) {
        sbin[tid] = b_ih[(size_t)f * GG + 128 + tid];
        sbhn[tid] = b_hh[(size_t)f * GG + 128 + tid];
    }
    for (int idx = tid; idx < 2 * 64 * HT_S; idx += 128) hbuf[idx] = 0.0f;
    __syncthreads();

    {
        const float wir0 = swih[j0],       wir1 = swih[j0 + 1];
        const float wiz0 = swih[64 + j0],  wiz1 = swih[64 + j0 + 1];
        const float win0 = swih[128 + j0], win1 = swih[128 + j0 + 1];
        const float br0 = sbrz[j0],      br1 = sbrz[j0 + 1];
        const float bz0 = sbrz[64 + j0], bz1 = sbrz[64 + j0 + 1];
        const float bn0 = sbin[j0],      bn1 = sbin[j0 + 1];
        const float bh0 = sbhn[j0],      bh1 = sbhn[j0 + 1];

        float2 hp[2][4];
        #pragma unroll
        for (int jj = 0; jj < 2; ++jj)
            #pragma unroll
            for (int p = 0; p < 4; ++p) hp[jj][p] = make_float2(0.f, 0.f);

        const size_t gbase0 = ((size_t)f * BB + b0 + bloc) * TT * HH + j0;

        for (int tc = 0; tc < TT / XCH; ++tc) {
            for (int idx = tid; idx < XCH * 32; idx += 128) {
                const int tt = idx >> 5, bb = idx & 31;
                sxc[idx] = x[(size_t)(tc * XCH + tt) * BB * FF + (size_t)(b0 + bb) * FF + f];
            }
            __syncthreads();

            for (int tl = 0; tl < XCH; ++tl) {
                const int t = tc * XCH + tl;
                const float* hc = hbuf + (t & 1) * 64 * HT_S;
                float* hn = hbuf + ((t & 1) ^ 1) * 64 * HT_S;

                unsigned long long accR[2][4], accZ[2][4], accN[2][4];
                #pragma unroll
                for (int jj = 0; jj < 2; ++jj)
                    #pragma unroll
                    for (int p = 0; p < 4; ++p) { accR[jj][p] = 0ull; accZ[jj][p] = 0ull; accN[jj][p] = 0ull; }

                #pragma unroll 4
                for (int k = 0; k < HH; ++k) {
                    const float* hrow = hc + k * HT_S + bloc;
                    unsigned long long hv[4];
                    #pragma unroll
                    for (int p = 0; p < 4; ++p) hv[p] = *(const unsigned long long*)(hrow + 2 * p);
                    const float* wrow = wT + k * WT_S + j0;
                    const float2 wr = *(const float2*)(wrow);
                    const float2 wz = *(const float2*)(wrow + 64);
                    const float2 wn = *(const float2*)(wrow + 128);
                    const unsigned long long wr0 = dup2(wr.x), wr1 = dup2(wr.y);
                    const unsigned long long wz0 = dup2(wz.x), wz1 = dup2(wz.y);
                    const unsigned long long wn0 = dup2(wn.x), wn1 = dup2(wn.y);
                    #pragma unroll
                    for (int p = 0; p < 4; ++p) {
                        accR[0][p] = ffma2(wr0, hv[p], accR[0][p]);
                        accR[1][p] = ffma2(wr1, hv[p], accR[1][p]);
                        accZ[0][p] = ffma2(wz0, hv[p], accZ[0][p]);
                        accZ[1][p] = ffma2(wz1, hv[p], accZ[1][p]);
                        accN[0][p] = ffma2(wn0, hv[p], accN[0][p]);
                        accN[1][p] = ffma2(wn1, hv[p], accN[1][p]);
                    }
                }

                const size_t gb = gbase0 + (size_t)t * HH;
                #pragma unroll
                for (int p = 0; p < 4; ++p) {
                    const float2 xv = *(const float2*)&sxc[tl * 32 + bloc + 2 * p];
                    const float2 aR0 = u2f(accR[0][p]), aR1 = u2f(accR[1][p]);
                    const float2 aZ0 = u2f(accZ[0][p]), aZ1 = u2f(accZ[1][p]);
                    const float2 aN0 = u2f(accN[0][p]), aN1 = u2f(accN[1][p]);

                    const float r00 = fmaf(0.5f, tanh_ap(fmaf(xv.x, wir0, aR0.x + br0)), 0.5f);
                    const float r0y = fmaf(0.5f, tanh_ap(fmaf(xv.y, wir0, aR0.y + br0)), 0.5f);
                    const float z00 = fmaf(0.5f, tanh_ap(fmaf(xv.x, wiz0, aZ0.x + bz0)), 0.5f);
                    const float z0y = fmaf(0.5f, tanh_ap(fmaf(xv.y, wiz0, aZ0.y + bz0)), 0.5f);
                    const float n00 = tanh_ap(fmaf(xv.x, win0, fmaf(r00, aN0.x + bh0, bn0)));
                    const float n0y = tanh_ap(fmaf(xv.y, win0, fmaf(r0y, aN0.y + bh0, bn0)));
                    const float h00 = fmaf(z00, hp[0][p].x - n00, n00);
                    const float h0y = fmaf(z0y, hp[0][p].y - n0y, n0y);

                    const float r10 = fmaf(0.5f, tanh_ap(fmaf(xv.x, wir1, aR1.x + br1)), 0.5f);
                    const float r1y = fmaf(0.5f, tanh_ap(fmaf(xv.y, wir1, aR1.y + br1)), 0.5f);
                    const float z10 = fmaf(0.5f, tanh_ap(fmaf(xv.x, wiz1, aZ1.x + bz1)), 0.5f);
                    const float z1y = fmaf(0.5f, tanh_ap(fmaf(xv.y, wiz1, aZ1.y + bz1)), 0.5f);
                    const float n10 = tanh_ap(fmaf(xv.x, win1, fmaf(r10, aN1.x + bh1, bn1)));
                    const float n1y = tanh_ap(fmaf(xv.y, win1, fmaf(r1y, aN1.y + bh1, bn1)));
                    const float h10 = fmaf(z10, hp[1][p].x - n10, n10);
                    const float h1y = fmaf(z1y, hp[1][p].y - n1y, n1y);

                    hp[0][p] = make_float2(h00, h0y);
                    hp[1][p] = make_float2(h10, h1y);

                    *(float2*)&hn[j0 * HT_S + bloc + 2 * p] = make_float2(h00, h0y);
                    *(float2*)&hn[(j0 + 1) * HT_S + bloc + 2 * p] = make_float2(h10, h1y);
                    *(float2*)&g_hs[gb + (size_t)(2 * p) * TT * HH] = make_float2(h00, h10);
                    *(float2*)&g_hs[gb + (size_t)(2 * p + 1) * TT * HH] = make_float2(h0y, h1y);
                }
                __syncthreads();
            }
        }
    }

    // ================= fused time-attention (max-free softmax) =================
    float* sh   = wT;                 // 128*65 floats (wT dead)
    float* sWt  = hbuf;               // 512
    float* sWx  = hbuf + 512;         // 512
    float* sq   = hbuf + 1024;        // 8
    float* sa   = hbuf + 1032;        // 128
    float* red2 = hbuf + 1160;        // 4
    float* pare = hbuf + 1168;        // 128

    for (int idx = tid; idx < HH * AH; idx += 128) {
        sWt[idx] = att_Wt[(size_t)f * HH * AH + idx];
        sWx[idx] = att_Wx[(size_t)f * HH * AH + idx];
    }
    const float sr = sigmoidf_(att_rate[f]);
    __syncthreads();

    for (int bb = 0; bb < 32; ++bb) {
        const int bg = b0 + bb;
        const float4* hsrc4 = (const float4*)(g_hs + ((size_t)(f * BB + bg)) * TT * HH);
        #pragma unroll 4
        for (int idx = tid; idx < TT * HH / 4; idx += 128) {
            float4 v = hsrc4[idx];
            const int row = idx >> 4;
            float* d = &sh[row * 65 + ((idx & 15) << 2)];
            d[0] = v.x; d[1] = v.y; d[2] = v.z; d[3] = v.w;
        }
        __syncthreads();

        if (tid < AH) {
            float q = 0.f;
            for (int j = 0; j < HH; ++j) q += sh[(TT - 1) * 65 + j] * sWt[j * AH + tid];
            sq[tid] = q;
        }
        __syncthreads();

        const int t = tid;
        unsigned long long kv2[4] = {0ull, 0ull, 0ull, 0ull};
        #pragma unroll 4
        for (int j = 0; j < HH; ++j) {
            const unsigned long long hd = dup2(sh[t * 65 + j]);
            const unsigned long long* wp = (const unsigned long long*)&sWx[j * AH];
            kv2[0] = ffma2(wp[0], hd, kv2[0]);
            kv2[1] = ffma2(wp[1], hd, kv2[1]);
            kv2[2] = ffma2(wp[2], hd, kv2[2]);
            kv2[3] = ffma2(wp[3], hd, kv2[3]);
        }
        float dp = 0.f;
        #pragma unroll
        for (int c = 0; c < 4; ++c) {
            const float2 kc = u2f(kv2[c]);
            dp += sq[2 * c] * kc.x + sq[2 * c + 1] * kc.y;
        }

        const float sig = sigmoidf_(dp);
        const float decay = (float)(TT - t);
        const float denom = sr * (__logf(2.72f + (1.0f - sig)) * decay);
        const float e = fmaxf(__fdividef(sig, denom), 0.0f);
        const float ex = __expf(e);

        float s = ex;
        #pragma unroll
        for (int o = 16; o > 0; o >>= 1) s += __shfl_xor_sync(0xffffffffu, s, o);
        if ((tid & 31) == 0) red2[tid >> 5] = s;
        __syncthreads();
        s = red2[0] + red2[1] + red2[2] + red2[3];
        sa[t] = ex * __fdividef(1.0f, s);
        __syncthreads();

        const int hidx = tid & 63, part = tid >> 6;
        float acc = 0.f;
        const int t0 = part * 64;
        for (int tt2 = t0; tt2 < t0 + 64; ++tt2) acc += sa[tt2] * sh[tt2 * 65 + hidx];
        pare[tid] = acc;
        __syncthreads();
        if (tid < 64)
            g_emb[((size_t)bg * FF + f) * HH + tid] = pare[tid] + pare[tid + 64];
        __syncthreads();
    }
}

// =====================================================================
// Kernel C: per-batch MHA + FFN + FinalAttention + head.
// launch_bounds(256,2) -> 128-reg budget; packed-f32x2 gemm76s with
// unrolled k-loop for deep load batching.
// =====================================================================
#define BUFSZ 4864   // 76*64

__device__ __forceinline__ void gemm76s(const float* __restrict__ sIn,
                                        const float* __restrict__ sW,
                                        const float* __restrict__ gB,
                                        float* __restrict__ sOut,
                                        int tid, bool addTo, bool relu)
{
    const int j0 = (tid & 31) * 2;
    const int i0 = tid >> 5;
    unsigned long long acc2[10];
    #pragma unroll
    for (int r = 0; r < 10; ++r) acc2[r] = 0ull;
    #pragma unroll 2
    for (int k = 0; k < HH; ++k) {
        const unsigned long long w2 = *(const unsigned long long*)&sW[k * 64 + j0];
        float sv[10];
        #pragma unroll
        for (int r = 0; r < 10; ++r) sv[r] = sIn[(i0 + 8 * r) * 64 + k];
        #pragma unroll
        for (int r = 0; r < 10; ++r)
            acc2[r] = ffma2(w2, dup2(sv[r]), acc2[r]);
    }
    float2 bj = make_float2(0.f, 0.f);
    if (gB) bj = *(const float2*)&gB[j0];
    #pragma unroll
    for (int r = 0; r < 10; ++r) {
        const int i = i0 + 8 * r;
        if (i < FF) {
            const float2 a = u2f(acc2[r]);
            float vx = a.x + bj.x;
            float vy = a.y + bj.y;
            if (addTo) { vx += sOut[i * 64 + j0]; vy += sOut[i * 64 + j0 + 1]; }
            if (relu)  { vx = fmaxf(vx, 0.f);     vy = fmaxf(vy, 0.f); }
            sOut[i * 64 + j0] = vx;
            sOut[i * 64 + j0 + 1] = vy;
        }
    }
}

__device__ __forceinline__ void stageW(const float* __restrict__ g,
                                       float* __restrict__ s, int tid)
{
    const float4* g4 = (const float4*)g;
    float4* s4 = (float4*)s;
    for (int i = tid; i < 1024; i += 256) s4[i] = g4[i];
}

#define SMEM_C_FLOATS (4 * BUFSZ + 5888)

__global__ void __launch_bounds__(256, 2) mix_kernel(
    const float* __restrict__ wq, const float* __restrict__ bq,
    const float* __restrict__ wk, const float* __restrict__ bk,
    const float* __restrict__ wv, const float* __restrict__ bv,
    const float* __restrict__ wo, const float* __restrict__ bo,
    const float* __restrict__ w1, const float* __restrict__ b1,
    const float* __restrict__ w2, const float* __restrict__ b2,
    const float* __restrict__ fwq, const float* __restrict__ fbq,
    const float* __restrict__ fwk, const float* __restrict__ fbk,
    const float* __restrict__ fwv, const float* __restrict__ fbv,
    const float* __restrict__ o0w, const float* __restrict__ o0b,
    const float* __restrict__ o1w, const float* __restrict__ o1b,
    float* __restrict__ out)
{
    extern __shared__ float sm[];
    float* sE = sm;
    float* sQ = sE + BUFSZ;
    float* sK = sQ + BUFSZ;
    float* sV = sK + BUFSZ;
    float* sS = sV + BUFSZ;     // 5888

    const int tid = threadIdx.x;
    const int b = blockIdx.x;
    float* rinv = sS + 5776;

    {
        const float4* esrc = (const float4*)(g_emb + (size_t)b * FF * HH);
        float4* d4 = (float4*)sE;
        for (int idx = tid; idx < FF * HH / 4; idx += 256) d4[idx] = esrc[idx];
    }
    __syncthreads();

    stageW(wq, sS, tid); __syncthreads();
    gemm76s(sE, sS, bq, sQ, tid, false, false); __syncthreads();
    stageW(wk, sS, tid); __syncthreads();
    gemm76s(sE, sS, bk, sK, tid, false, false); __syncthreads();
    stageW(wv, sS, tid); __syncthreads();
    gemm76s(sE, sS, bv, sV, tid, false, false); __syncthreads();

    // MHA over F, max-free softmax
    for (int h = 0; h < NHEAD; ++h) {
        const int hd = h * 16;
        for (int idx = tid; idx < FF * FF; idx += 256) {
            const int i = idx / FF, jf = idx % FF;
            const float4* qp = (const float4*)&sQ[i * HH + hd];
            const float4* kp = (const float4*)&sK[jf * HH + hd];
            float acc = 0.f;
            #pragma unroll
            for (int c = 0; c < 4; ++c) {
                const float4 qv = qp[c], kv = kp[c];
                acc += qv.x * kv.x + qv.y * kv.y + qv.z * kv.z + qv.w * kv.w;
            }
            sS[idx] = __expf(acc * 0.25f);
        }
        __syncthreads();
        if (tid < FF) {
            float s = 0.f;
            #pragma unroll 4
            for (int jf = 0; jf < FF; ++jf) s += sS[tid * FF + jf];
            rinv[tid] = __fdividef(1.0f, s);
        }
        __syncthreads();
        for (int idx = tid; idx < FF * 16; idx += 256) {
            const int i = idx / 16, d = idx % 16;
            const float* srow = &sS[i * FF];
            const float* vcol = &sV[hd + d];
            float acc = 0.f;
            #pragma unroll 4
            for (int jf = 0; jf < FF; ++jf) acc += srow[jf] * vcol[jf * HH];
            sQ[i * HH + hd + d] = acc * rinv[i];
        }
        __syncthreads();
    }

    stageW(wo, sS, tid); __syncthreads();
    gemm76s(sQ, sS, bo, sE, tid, true, false); __syncthreads();

    // FFN: DFF in 4 chunks of 64
    for (int c = 0; c < 4; ++c) {
        for (int idx = tid; idx < 1024; idx += 256) {
            const int k = idx >> 4, j4 = idx & 15;
            *(float4*)&sS[k * 64 + 4 * j4] = *(const float4*)&w1[k * DFF + 64 * c + 4 * j4];
        }
        {
            const float4* g4 = (const float4*)(w2 + 4096 * c);
            float4* s4 = (float4*)sK;
            for (int i = tid; i < 1024; i += 256) s4[i] = g4[i];
        }
        __syncthreads();
        gemm76s(sE, sS, b1 + 64 * c, sQ, tid, false, true);
        __syncthreads();
        gemm76s(sQ, sK, (c == 0) ? b2 : nullptr, sV, tid, c > 0, false);
        __syncthreads();
    }
    for (int idx = tid; idx < FF * HH; idx += 256) sE[idx] += sV[idx];
    __syncthreads();

    // FinalAttentionQKV ('mul'), max-free softmax + warp-reduced sum
    float* fqS = sS + 4608;
    float* wS  = sS + 4768;
    float* vS  = sS + 4848;
    float* uS  = sS + 4912;
    float* msS = sS + 4976;

    if (tid < HH) {
        float acc = fbq[tid];
        for (int k = 0; k < HH; ++k) acc += sE[(FF - 1) * HH + k] * fwq[k * HH + tid];
        fqS[tid] = acc;
    }
    stageW(fwk, sS, tid); __syncthreads();
    gemm76s(sE, sS, fbk, sQ, tid, false, false); __syncthreads();
    stageW(fwv, sS, tid); __syncthreads();
    gemm76s(sE, sS, fbv, sK, tid, false, false); __syncthreads();

    if (tid < FF) {
        float acc = 0.f;
        for (int j = 0; j < HH; ++j) acc += sQ[tid * HH + j] * fqS[j];
        wS[tid] = __expf(acc);
    }
    __syncthreads();
    if (tid < 32) {
        float s = wS[tid] + wS[tid + 32] + ((tid + 64 < FF) ? wS[tid + 64] : 0.f);
        #pragma unroll
        for (int o = 16; o > 0; o >>= 1) s += __shfl_xor_sync(0xffffffffu, s, o);
        if (tid == 0) msS[0] = __fdividef(1.0f, s);
    }
    __syncthreads();
    const float inv = msS[0];
    if (tid < HH) {
        float acc = 0.f;
        for (int i = 0; i < FF; ++i) acc += (wS[i] * inv) * sK[i * HH + tid];
        vS[tid] = acc;
    }
    __syncthreads();
    if (tid < HH) {
        float acc = o0b[tid];
        for (int k = 0; k < HH; ++k) acc += vS[k] * o0w[k * HH + tid];
        uS[tid] = fmaxf(acc, 0.0f);
    }
    __syncthreads();
    if (tid == 0) {
        float acc = o1b[0];
        for (int j = 0; j < HH; ++j) acc += uS[j] * o1w[j];
        out[b] = sigmoidf_(acc);
    }
}

// =====================================================================
extern "C" void kernel_launch(void* const* d_in, const int* in_sizes, int n_in,
                              void* d_out, int out_size)
{
    const float* x     = (const float*)d_in[0];
    const float* wih   = (const float*)d_in[1];
    const float* whh   = (const float*)d_in[2];
    const float* bih   = (const float*)d_in[3];
    const float* bhh   = (const float*)d_in[4];
    const float* aWt   = (const float*)d_in[5];
    const float* aWx   = (const float*)d_in[6];
    const float* arate = (const float*)d_in[7];
    const float* mwq = (const float*)d_in[8],  *mbq = (const float*)d_in[9];
    const float* mwk = (const float*)d_in[10], *mbk = (const float*)d_in[11];
    const float* mwv = (const float*)d_in[12], *mbv = (const float*)d_in[13];
    const float* mwo = (const float*)d_in[14], *mbo = (const float*)d_in[15];
    const float* fw1 = (const float*)d_in[16], *fb1 = (const float*)d_in[17];
    const float* fw2 = (const float*)d_in[18], *fb2 = (const float*)d_in[19];
    const float* fwq = (const float*)d_in[20], *fbq = (const float*)d_in[21];
    const float* fwk = (const float*)d_in[22], *fbk = (const float*)d_in[23];
    const float* fwv = (const float*)d_in[24], *fbv = (const float*)d_in[25];
    const float* o0w = (const float*)d_in[26], *o0b = (const float*)d_in[27];
    const float* o1w = (const float*)d_in[28], *o1b = (const float*)d_in[29];
    float* out = (float*)d_out;

    const int smemA = SMEM_A_FLOATS * 4;
    const int smemC = SMEM_C_FLOATS * 4;
    cudaFuncSetAttribute(gru_attn_kernel, cudaFuncAttributeMaxDynamicSharedMemorySize, smemA);
    cudaFuncSetAttribute(mix_kernel, cudaFuncAttributeMaxDynamicSharedMemorySize, smemC);

    gru_attn_kernel<<<dim3(8, FF), 128, smemA>>>(x, wih, whh, bih, bhh, aWt, aWx, arate);
    mix_kernel<<<BB, 256, smemC>>>(mwq, mbq, mwk, mbk, mwv, mbv, mwo, mbo,
                                   fw1, fb1, fw2, fb2,
                                   fwq, fbq, fwk, fbk, fwv, fbv,
                                   o0w, o0b, o1w, o1b, out);
}

// round 15
// speedup vs baseline: 1.5571x; 1.5571x over previous
#include <cuda_runtime.h>
#include <cuda_bf16.h>
#include <cstdint>

#define TT 128
#define BB 256
#define FF 76
#define HH 64
#define GG 192   // 3*H
#define NHEAD 4
#define DFF 256
#define AH 8

// ---------------- scratch (device globals; no runtime allocation) ----------------
__device__ float g_hs[(size_t)FF * BB * TT * HH];   // [F][B][T][H]
__device__ float g_emb[(size_t)BB * FF * HH];       // [B][F][H]

// ---------------- helpers ----------------
__device__ __forceinline__ float sigmoidf_(float x) {
    return __fdividef(1.0f, 1.0f + __expf(-x));
}
__device__ __forceinline__ float tanh_ap(float x) {
    float y;
    asm("tanh.approx.f32 %0, %1;" : "=f"(y) : "f"(x));
    return y;
}
__device__ __forceinline__ unsigned long long ffma2(unsigned long long a,
                                                    unsigned long long b,
                                                    unsigned long long c) {
    unsigned long long d;
    asm("fma.rn.f32x2 %0, %1, %2, %3;" : "=l"(d) : "l"(a), "l"(b), "l"(c));
    return d;
}
__device__ __forceinline__ unsigned long long dup2(float v) {
    unsigned long long d;
    asm("mov.b64 %0, {%1, %1};" : "=l"(d) : "f"(v));
    return d;
}
__device__ __forceinline__ float2 u2f(unsigned long long u) {
    return *(float2*)&u;
}

// =====================================================================
// Kernel A: fused per-feature GRU scan + per-(f,b) time attention.
// (EXACT R13 code — GRU at FFMA2 floor, tail measured good)
// =====================================================================
#define WT_S 194          // wT row stride (floats)
#define HT_S 34           // h row stride (floats, even)
#define XCH 32            // t-chunk
#define SMEM_A_FLOATS (64 * WT_S + 2 * 64 * HT_S + GG + 128 + 64 + 64 + XCH * 32)

__global__ void __launch_bounds__(128, 3) gru_attn_kernel(
    const float* __restrict__ x,        // (T,B,F)
    const float* __restrict__ w_ih,     // (F,3H)
    const float* __restrict__ w_hh,     // (F,3H,H)
    const float* __restrict__ b_ih,     // (F,3H)
    const float* __restrict__ b_hh,     // (F,3H)
    const float* __restrict__ att_Wt,   // (F,H,AH)
    const float* __restrict__ att_Wx,   // (F,H,AH)
    const float* __restrict__ att_rate) // (F,)
{
    extern __shared__ float sm[];
    float* wT   = sm;                          // [64][194]
    float* hbuf = wT + 64 * WT_S;              // 2 x [64][34]
    float* swih = hbuf + 2 * 64 * HT_S;        // 192 (*0.5 for first 128)
    float* sbrz = swih + GG;                   // 128
    float* sbin = sbrz + 128;                  // 64
    float* sbhn = sbin + 64;                   // 64
    float* sxc  = sbhn + 64;                   // XCH*32

    const int f  = blockIdx.y;
    const int b0 = blockIdx.x * 32;
    const int tid = threadIdx.x;
    const int tx = tid & 31, ty = tid >> 5;
    const int j0 = 2 * tx;
    const int bloc = 8 * ty;

    const float* whf = w_hh + (size_t)f * GG * HH;
    for (int idx = tid; idx < GG * HH; idx += 128) {
        const int g = idx >> 6, k = idx & 63;
        const float s = (g < 128) ? 0.5f : 1.0f;
        wT[k * WT_S + g] = whf[idx] * s;
    }
    for (int idx = tid; idx < GG; idx += 128) {
        const float s = (idx < 128) ? 0.5f : 1.0f;
        swih[idx] = w_ih[(size_t)f * GG + idx] * s;
    }
    if (tid < 128) sbrz[tid] = 0.5f * (b_ih[(size_t)f * GG + tid] + b_hh[(size_t)f * GG + tid]);
    if (tid < 64) {
        sbin[tid] = b_ih[(size_t)f * GG + 128 + tid];
        sbhn[tid] = b_hh[(size_t)f * GG + 128 + tid];
    }
    for (int idx = tid; idx < 2 * 64 * HT_S; idx += 128) hbuf[idx] = 0.0f;
    __syncthreads();

    {
        const float wir0 = swih[j0],       wir1 = swih[j0 + 1];
        const float wiz0 = swih[64 + j0],  wiz1 = swih[64 + j0 + 1];
        const float win0 = swih[128 + j0], win1 = swih[128 + j0 + 1];
        const float br0 = sbrz[j0],      br1 = sbrz[j0 + 1];
        const float bz0 = sbrz[64 + j0], bz1 = sbrz[64 + j0 + 1];
        const float bn0 = sbin[j0],      bn1 = sbin[j0 + 1];
        const float bh0 = sbhn[j0],      bh1 = sbhn[j0 + 1];

        float2 hp[2][4];
        #pragma unroll
        for (int jj = 0; jj < 2; ++jj)
            #pragma unroll
            for (int p = 0; p < 4; ++p) hp[jj][p] = make_float2(0.f, 0.f);

        const size_t gbase0 = ((size_t)f * BB + b0 + bloc) * TT * HH + j0;

        for (int tc = 0; tc < TT / XCH; ++tc) {
            for (int idx = tid; idx < XCH * 32; idx += 128) {
                const int tt = idx >> 5, bb = idx & 31;
                sxc[idx] = x[(size_t)(tc * XCH + tt) * BB * FF + (size_t)(b0 + bb) * FF + f];
            }
            __syncthreads();

            for (int tl = 0; tl < XCH; ++tl) {
                const int t = tc * XCH + tl;
                const float* hc = hbuf + (t & 1) * 64 * HT_S;
                float* hn = hbuf + ((t & 1) ^ 1) * 64 * HT_S;

                unsigned long long accR[2][4], accZ[2][4], accN[2][4];
                #pragma unroll
                for (int jj = 0; jj < 2; ++jj)
                    #pragma unroll
                    for (int p = 0; p < 4; ++p) { accR[jj][p] = 0ull; accZ[jj][p] = 0ull; accN[jj][p] = 0ull; }

                #pragma unroll 4
                for (int k = 0; k < HH; ++k) {
                    const float* hrow = hc + k * HT_S + bloc;
                    unsigned long long hv[4];
                    #pragma unroll
                    for (int p = 0; p < 4; ++p) hv[p] = *(const unsigned long long*)(hrow + 2 * p);
                    const float* wrow = wT + k * WT_S + j0;
                    const float2 wr = *(const float2*)(wrow);
                    const float2 wz = *(const float2*)(wrow + 64);
                    const float2 wn = *(const float2*)(wrow + 128);
                    const unsigned long long wr0 = dup2(wr.x), wr1 = dup2(wr.y);
                    const unsigned long long wz0 = dup2(wz.x), wz1 = dup2(wz.y);
                    const unsigned long long wn0 = dup2(wn.x), wn1 = dup2(wn.y);
                    #pragma unroll
                    for (int p = 0; p < 4; ++p) {
                        accR[0][p] = ffma2(wr0, hv[p], accR[0][p]);
                        accR[1][p] = ffma2(wr1, hv[p], accR[1][p]);
                        accZ[0][p] = ffma2(wz0, hv[p], accZ[0][p]);
                        accZ[1][p] = ffma2(wz1, hv[p], accZ[1][p]);
                        accN[0][p] = ffma2(wn0, hv[p], accN[0][p]);
                        accN[1][p] = ffma2(wn1, hv[p], accN[1][p]);
                    }
                }

                const size_t gb = gbase0 + (size_t)t * HH;
                #pragma unroll
                for (int p = 0; p < 4; ++p) {
                    const float2 xv = *(const float2*)&sxc[tl * 32 + bloc + 2 * p];
                    const float2 aR0 = u2f(accR[0][p]), aR1 = u2f(accR[1][p]);
                    const float2 aZ0 = u2f(accZ[0][p]), aZ1 = u2f(accZ[1][p]);
                    const float2 aN0 = u2f(accN[0][p]), aN1 = u2f(accN[1][p]);

                    const float r00 = fmaf(0.5f, tanh_ap(fmaf(xv.x, wir0, aR0.x + br0)), 0.5f);
                    const float r0y = fmaf(0.5f, tanh_ap(fmaf(xv.y, wir0, aR0.y + br0)), 0.5f);
                    const float z00 = fmaf(0.5f, tanh_ap(fmaf(xv.x, wiz0, aZ0.x + bz0)), 0.5f);
                    const float z0y = fmaf(0.5f, tanh_ap(fmaf(xv.y, wiz0, aZ0.y + bz0)), 0.5f);
                    const float n00 = tanh_ap(fmaf(xv.x, win0, fmaf(r00, aN0.x + bh0, bn0)));
                    const float n0y = tanh_ap(fmaf(xv.y, win0, fmaf(r0y, aN0.y + bh0, bn0)));
                    const float h00 = fmaf(z00, hp[0][p].x - n00, n00);
                    const float h0y = fmaf(z0y, hp[0][p].y - n0y, n0y);

                    const float r10 = fmaf(0.5f, tanh_ap(fmaf(xv.x, wir1, aR1.x + br1)), 0.5f);
                    const float r1y = fmaf(0.5f, tanh_ap(fmaf(xv.y, wir1, aR1.y + br1)), 0.5f);
                    const float z10 = fmaf(0.5f, tanh_ap(fmaf(xv.x, wiz1, aZ1.x + bz1)), 0.5f);
                    const float z1y = fmaf(0.5f, tanh_ap(fmaf(xv.y, wiz1, aZ1.y + bz1)), 0.5f);
                    const float n10 = tanh_ap(fmaf(xv.x, win1, fmaf(r10, aN1.x + bh1, bn1)));
                    const float n1y = tanh_ap(fmaf(xv.y, win1, fmaf(r1y, aN1.y + bh1, bn1)));
                    const float h10 = fmaf(z10, hp[1][p].x - n10, n10);
                    const float h1y = fmaf(z1y, hp[1][p].y - n1y, n1y);

                    hp[0][p] = make_float2(h00, h0y);
                    hp[1][p] = make_float2(h10, h1y);

                    *(float2*)&hn[j0 * HT_S + bloc + 2 * p] = make_float2(h00, h0y);
                    *(float2*)&hn[(j0 + 1) * HT_S + bloc + 2 * p] = make_float2(h10, h1y);
                    *(float2*)&g_hs[gb + (size_t)(2 * p) * TT * HH] = make_float2(h00, h10);
                    *(float2*)&g_hs[gb + (size_t)(2 * p + 1) * TT * HH] = make_float2(h0y, h1y);
                }
                __syncthreads();
            }
        }
    }

    // ================= fused time-attention (max-free softmax) =================
    float* sh   = wT;                 // 128*65 floats (wT dead)
    float* sWt  = hbuf;               // 512
    float* sWx  = hbuf + 512;         // 512
    float* sq   = hbuf + 1024;        // 8
    float* sa   = hbuf + 1032;        // 128
    float* red2 = hbuf + 1160;        // 4
    float* pare = hbuf + 1168;        // 128

    for (int idx = tid; idx < HH * AH; idx += 128) {
        sWt[idx] = att_Wt[(size_t)f * HH * AH + idx];
        sWx[idx] = att_Wx[(size_t)f * HH * AH + idx];
    }
    const float sr = sigmoidf_(att_rate[f]);
    __syncthreads();

    for (int bb = 0; bb < 32; ++bb) {
        const int bg = b0 + bb;
        const float4* hsrc4 = (const float4*)(g_hs + ((size_t)(f * BB + bg)) * TT * HH);
        #pragma unroll 4
        for (int idx = tid; idx < TT * HH / 4; idx += 128) {
            float4 v = hsrc4[idx];
            const int row = idx >> 4;
            float* d = &sh[row * 65 + ((idx & 15) << 2)];
            d[0] = v.x; d[1] = v.y; d[2] = v.z; d[3] = v.w;
        }
        __syncthreads();

        if (tid < AH) {
            float q = 0.f;
            for (int j = 0; j < HH; ++j) q += sh[(TT - 1) * 65 + j] * sWt[j * AH + tid];
            sq[tid] = q;
        }
        __syncthreads();

        const int t = tid;
        unsigned long long kv2[4] = {0ull, 0ull, 0ull, 0ull};
        #pragma unroll 4
        for (int j = 0; j < HH; ++j) {
            const unsigned long long hd = dup2(sh[t * 65 + j]);
            const unsigned long long* wp = (const unsigned long long*)&sWx[j * AH];
            kv2[0] = ffma2(wp[0], hd, kv2[0]);
            kv2[1] = ffma2(wp[1], hd, kv2[1]);
            kv2[2] = ffma2(wp[2], hd, kv2[2]);
            kv2[3] = ffma2(wp[3], hd, kv2[3]);
        }
        float dp = 0.f;
        #pragma unroll
        for (int c = 0; c < 4; ++c) {
            const float2 kc = u2f(kv2[c]);
            dp += sq[2 * c] * kc.x + sq[2 * c + 1] * kc.y;
        }

        const float sig = sigmoidf_(dp);
        const float decay = (float)(TT - t);
        const float denom = sr * (__logf(2.72f + (1.0f - sig)) * decay);
        const float e = fmaxf(__fdividef(sig, denom), 0.0f);
        const float ex = __expf(e);

        float s = ex;
        #pragma unroll
        for (int o = 16; o > 0; o >>= 1) s += __shfl_xor_sync(0xffffffffu, s, o);
        if ((tid & 31) == 0) red2[tid >> 5] = s;
        __syncthreads();
        s = red2[0] + red2[1] + red2[2] + red2[3];
        sa[t] = ex * __fdividef(1.0f, s);
        __syncthreads();

        const int hidx = tid & 63, part = tid >> 6;
        float acc = 0.f;
        const int t0 = part * 64;
        for (int tt2 = t0; tt2 < t0 + 64; ++tt2) acc += sa[tt2] * sh[tt2 * 65 + hidx];
        pare[tid] = acc;
        __syncthreads();
        if (tid < 64)
            g_emb[((size_t)bg * FF + f) * HH + tid] = pare[tid] + pare[tid + 64];
        __syncthreads();
    }
}

// =====================================================================
// Kernel C: per-batch MHA + FFN + FinalAttention + head.
// TWO batches per block: weight stages + barriers amortized 2x, fused
// dual-batch GEMM doubles ILP per k-step. grid 128, 1 block/SM (~200KB smem).
// =====================================================================
#define BUFSZ 4864    // 76*64
#define SCOR  5776    // 76*76

// dual-batch 76x64 @ 64x64 from smem weights
__device__ __forceinline__ void gemm76s2(const float* __restrict__ sIn0,
                                         const float* __restrict__ sIn1,
                                         const float* __restrict__ sW,
                                         const float* __restrict__ gB,
                                         float* __restrict__ sOut0,
                                         float* __restrict__ sOut1,
                                         int tid, bool addTo, bool relu)
{
    const int j0 = (tid & 31) * 2;
    const int i0 = tid >> 5;
    float a0x[10], a0y[10], a1x[10], a1y[10];
    #pragma unroll
    for (int r = 0; r < 10; ++r) { a0x[r] = 0.f; a0y[r] = 0.f; a1x[r] = 0.f; a1y[r] = 0.f; }
    for (int k = 0; k < HH; ++k) {
        const float2 w = *(const float2*)&sW[k * 64 + j0];
        #pragma unroll
        for (int r = 0; r < 10; ++r) {
            const float s0 = sIn0[(i0 + 8 * r) * 64 + k];
            const float s1 = sIn1[(i0 + 8 * r) * 64 + k];
            a0x[r] += s0 * w.x; a0y[r] += s0 * w.y;
            a1x[r] += s1 * w.x; a1y[r] += s1 * w.y;
        }
    }
    float2 bj = make_float2(0.f, 0.f);
    if (gB) bj = *(const float2*)&gB[j0];
    #pragma unroll
    for (int r = 0; r < 10; ++r) {
        const int i = i0 + 8 * r;
        if (i < FF) {
            float v0x = a0x[r] + bj.x, v0y = a0y[r] + bj.y;
            float v1x = a1x[r] + bj.x, v1y = a1y[r] + bj.y;
            if (addTo) {
                v0x += sOut0[i * 64 + j0]; v0y += sOut0[i * 64 + j0 + 1];
                v1x += sOut1[i * 64 + j0]; v1y += sOut1[i * 64 + j0 + 1];
            }
            if (relu) {
                v0x = fmaxf(v0x, 0.f); v0y = fmaxf(v0y, 0.f);
                v1x = fmaxf(v1x, 0.f); v1y = fmaxf(v1y, 0.f);
            }
            sOut0[i * 64 + j0] = v0x; sOut0[i * 64 + j0 + 1] = v0y;
            sOut1[i * 64 + j0] = v1x; sOut1[i * 64 + j0 + 1] = v1y;
        }
    }
}

__device__ __forceinline__ void stageW(const float* __restrict__ g,
                                       float* __restrict__ s, int tid)
{
    const float4* g4 = (const float4*)g;
    float4* s4 = (float4*)s;
    for (int i = tid; i < 1024; i += 256) s4[i] = g4[i];
}

#define SMEM_C_FLOATS (8 * BUFSZ + 2 * SCOR + 640)

__global__ void __launch_bounds__(256) mix_kernel(
    const float* __restrict__ wq, const float* __restrict__ bq,
    const float* __restrict__ wk, const float* __restrict__ bk,
    const float* __restrict__ wv, const float* __restrict__ bv,
    const float* __restrict__ wo, const float* __restrict__ bo,
    const float* __restrict__ w1, const float* __restrict__ b1,
    const float* __restrict__ w2, const float* __restrict__ b2,
    const float* __restrict__ fwq, const float* __restrict__ fbq,
    const float* __restrict__ fwk, const float* __restrict__ fbk,
    const float* __restrict__ fwv, const float* __restrict__ fbv,
    const float* __restrict__ o0w, const float* __restrict__ o0b,
    const float* __restrict__ o1w, const float* __restrict__ o1b,
    float* __restrict__ out)
{
    extern __shared__ float sm[];
    float* sE0 = sm;
    float* sE1 = sE0 + BUFSZ;
    float* sQ0 = sE1 + BUFSZ;
    float* sQ1 = sQ0 + BUFSZ;
    float* sK0 = sQ1 + BUFSZ;
    float* sK1 = sK0 + BUFSZ;
    float* sV0 = sK1 + BUFSZ;
    float* sV1 = sV0 + BUFSZ;
    float* sS0 = sV1 + BUFSZ;       // scores batch0 / weight staging (4096 < 5776)
    float* sS1 = sS0 + SCOR;        // scores batch1
    float* sX  = sS1 + SCOR;        // 640 scratch

    const int tid = threadIdx.x;
    const int b0 = 2 * blockIdx.x;

    // scratch layout
    float* rinv0 = sX;              // 76
    float* rinv1 = sX + 80;         // 76
    float* fq0   = sX + 160;        // 64
    float* fq1   = sX + 224;        // 64
    float* wS0   = sX + 288;        // 76
    float* wS1   = sX + 368;        // 76
    float* vS0   = sX + 448;        // 64
    float* vS1   = sX + 512;        // 64
    float* msS   = sX + 576;        // 2 (uS reuses fq slots)
    float* uS0   = fq0;             // reuse (fq dead by then)
    float* uS1   = fq1;

    {
        const float4* e0 = (const float4*)(g_emb + (size_t)b0 * FF * HH);
        const float4* e1 = (const float4*)(g_emb + (size_t)(b0 + 1) * FF * HH);
        float4* d0 = (float4*)sE0;
        float4* d1 = (float4*)sE1;
        for (int idx = tid; idx < FF * HH / 4; idx += 256) { d0[idx] = e0[idx]; d1[idx] = e1[idx]; }
    }
    __syncthreads();

    stageW(wq, sS0, tid); __syncthreads();
    gemm76s2(sE0, sE1, sS0, bq, sQ0, sQ1, tid, false, false); __syncthreads();
    stageW(wk, sS0, tid); __syncthreads();
    gemm76s2(sE0, sE1, sS0, bk, sK0, sK1, tid, false, false); __syncthreads();
    stageW(wv, sS0, tid); __syncthreads();
    gemm76s2(sE0, sE1, sS0, bv, sV0, sV1, tid, false, false); __syncthreads();

    // MHA over F, max-free softmax, both batches per phase
    for (int h = 0; h < NHEAD; ++h) {
        const int hd = h * 16;
        for (int idx = tid; idx < FF * FF; idx += 256) {
            const int i = idx / FF, jf = idx % FF;
            const float4* q0 = (const float4*)&sQ0[i * HH + hd];
            const float4* k0 = (const float4*)&sK0[jf * HH + hd];
            const float4* q1 = (const float4*)&sQ1[i * HH + hd];
            const float4* k1 = (const float4*)&sK1[jf * HH + hd];
            float a0 = 0.f, a1 = 0.f;
            #pragma unroll
            for (int c = 0; c < 4; ++c) {
                const float4 qv0 = q0[c], kv0 = k0[c];
                const float4 qv1 = q1[c], kv1 = k1[c];
                a0 += qv0.x * kv0.x + qv0.y * kv0.y + qv0.z * kv0.z + qv0.w * kv0.w;
                a1 += qv1.x * kv1.x + qv1.y * kv1.y + qv1.z * kv1.z + qv1.w * kv1.w;
            }
            sS0[idx] = __expf(a0 * 0.25f);
            sS1[idx] = __expf(a1 * 0.25f);
        }
        __syncthreads();
        if (tid < FF) {
            float s0 = 0.f, s1 = 0.f;
            for (int jf = 0; jf < FF; ++jf) { s0 += sS0[tid * FF + jf]; s1 += sS1[tid * FF + jf]; }
            rinv0[tid] = __fdividef(1.0f, s0);
            rinv1[tid] = __fdividef(1.0f, s1);
        }
        __syncthreads();
        for (int idx = tid; idx < FF * 16; idx += 256) {
            const int i = idx / 16, d = idx % 16;
            const float* r0 = &sS0[i * FF];
            const float* r1 = &sS1[i * FF];
            const float* v0 = &sV0[hd + d];
            const float* v1 = &sV1[hd + d];
            float a0 = 0.f, a1 = 0.f;
            for (int jf = 0; jf < FF; ++jf) { a0 += r0[jf] * v0[jf * HH]; a1 += r1[jf] * v1[jf * HH]; }
            sQ0[i * HH + hd + d] = a0 * rinv0[i];
            sQ1[i * HH + hd + d] = a1 * rinv1[i];
        }
        __syncthreads();
    }

    stageW(wo, sS0, tid); __syncthreads();
    gemm76s2(sQ0, sQ1, sS0, bo, sE0, sE1, tid, true, false); __syncthreads();

    // FFN: DFF in 4 chunks of 64; W1 chunk in sS0, W2 chunk in sK0 (dead)
    for (int c = 0; c < 4; ++c) {
        for (int idx = tid; idx < 1024; idx += 256) {
            const int k = idx >> 4, j4 = idx & 15;
            *(float4*)&sS0[k * 64 + 4 * j4] = *(const float4*)&w1[k * DFF + 64 * c + 4 * j4];
        }
        {
            const float4* g4 = (const float4*)(w2 + 4096 * c);
            float4* s4 = (float4*)sK0;
            for (int i = tid; i < 1024; i += 256) s4[i] = g4[i];
        }
        __syncthreads();
        gemm76s2(sE0, sE1, sS0, b1 + 64 * c, sQ0, sQ1, tid, false, true);
        __syncthreads();
        gemm76s2(sQ0, sQ1, sK0, (c == 0) ? b2 : nullptr, sV0, sV1, tid, c > 0, false);
        __syncthreads();
    }
    for (int idx = tid; idx < FF * HH; idx += 256) { sE0[idx] += sV0[idx]; sE1[idx] += sV1[idx]; }
    __syncthreads();

    // FinalAttentionQKV ('mul'), max-free softmax
    if (tid < HH) {
        float a0 = fbq[tid], a1 = fbq[tid];
        for (int k = 0; k < HH; ++k) {
            const float w = fwq[k * HH + tid];
            a0 += sE0[(FF - 1) * HH + k] * w;
            a1 += sE1[(FF - 1) * HH + k] * w;
        }
        fq0[tid] = a0; fq1[tid] = a1;
    }
    stageW(fwk, sS0, tid); __syncthreads();
    gemm76s2(sE0, sE1, sS0, fbk, sQ0, sQ1, tid, false, false); __syncthreads();
    stageW(fwv, sS0, tid); __syncthreads();
    gemm76s2(sE0, sE1, sS0, fbv, sK0, sK1, tid, false, false); __syncthreads();

    if (tid < FF) {
        float a0 = 0.f, a1 = 0.f;
        for (int j = 0; j < HH; ++j) {
            a0 += sQ0[tid * HH + j] * fq0[j];
            a1 += sQ1[tid * HH + j] * fq1[j];
        }
        wS0[tid] = __expf(a0);
        wS1[tid] = __expf(a1);
    }
    __syncthreads();
    if (tid < 32) {
        float s0 = wS0[tid] + wS0[tid + 32] + ((tid + 64 < FF) ? wS0[tid + 64] : 0.f);
        float s1 = wS1[tid] + wS1[tid + 32] + ((tid + 64 < FF) ? wS1[tid + 64] : 0.f);
        #pragma unroll
        for (int o = 16; o > 0; o >>= 1) {
            s0 += __shfl_xor_sync(0xffffffffu, s0, o);
            s1 += __shfl_xor_sync(0xffffffffu, s1, o);
        }
        if (tid == 0) { msS[0] = __fdividef(1.0f, s0); msS[1] = __fdividef(1.0f, s1); }
    }
    __syncthreads();
    if (tid < HH) {
        const float i0 = msS[0], i1 = msS[1];
        float a0 = 0.f, a1 = 0.f;
        for (int i = 0; i < FF; ++i) {
            a0 += wS0[i] * sK0[i * HH + tid];
            a1 += wS1[i] * sK1[i * HH + tid];
        }
        vS0[tid] = a0 * i0; vS1[tid] = a1 * i1;
    }
    __syncthreads();
    if (tid < HH) {
        float a0 = o0b[tid], a1 = o0b[tid];
        for (int k = 0; k < HH; ++k) {
            const float w = o0w[k * HH + tid];
            a0 += vS0[k] * w;
            a1 += vS1[k] * w;
        }
        uS0[tid] = fmaxf(a0, 0.0f);
        uS1[tid] = fmaxf(a1, 0.0f);
    }
    __syncthreads();
    if (tid < 2) {
        const float* u = (tid == 0) ? uS0 : uS1;
        float acc = o1b[0];
        for (int j = 0; j < HH; ++j) acc += u[j] * o1w[j];
        out[b0 + tid] = sigmoidf_(acc);
    }
}

// =====================================================================
extern "C" void kernel_launch(void* const* d_in, const int* in_sizes, int n_in,
                              void* d_out, int out_size)
{
    const float* x     = (const float*)d_in[0];
    const float* wih   = (const float*)d_in[1];
    const float* whh   = (const float*)d_in[2];
    const float* bih   = (const float*)d_in[3];
    const float* bhh   = (const float*)d_in[4];
    const float* aWt   = (const float*)d_in[5];
    const float* aWx   = (const float*)d_in[6];
    const float* arate = (const float*)d_in[7];
    const float* mwq = (const float*)d_in[8],  *mbq = (const float*)d_in[9];
    const float* mwk = (const float*)d_in[10], *mbk = (const float*)d_in[11];
    const float* mwv = (const float*)d_in[12], *mbv = (const float*)d_in[13];
    const float* mwo = (const float*)d_in[14], *mbo = (const float*)d_in[15];
    const float* fw1 = (const float*)d_in[16], *fb1 = (const float*)d_in[17];
    const float* fw2 = (const float*)d_in[18], *fb2 = (const float*)d_in[19];
    const float* fwq = (const float*)d_in[20], *fbq = (const float*)d_in[21];
    const float* fwk = (const float*)d_in[22], *fbk = (const float*)d_in[23];
    const float* fwv = (const float*)d_in[24], *fbv = (const float*)d_in[25];
    const float* o0w = (const float*)d_in[26], *o0b = (const float*)d_in[27];
    const float* o1w = (const float*)d_in[28], *o1b = (const float*)d_in[29];
    float* out = (float*)d_out;

    const int smemA = SMEM_A_FLOATS * 4;
    const int smemC = SMEM_C_FLOATS * 4;
    cudaFuncSetAttribute(gru_attn_kernel, cudaFuncAttributeMaxDynamicSharedMemorySize, smemA);
    cudaFuncSetAttribute(mix_kernel, cudaFuncAttributeMaxDynamicSharedMemorySize, smemC);

    gru_attn_kernel<<<dim3(8, FF), 128, smemA>>>(x, wih, whh, bih, bhh, aWt, aWx, arate);
    mix_kernel<<<BB / 2, 256, smemC>>>(mwq, mbq, mwk, mbk, mwv, mbv, mwo, mbo,
                                       fw1, fb1, fw2, fb2,
                                       fwq, fbq, fwk, fbk, fwv, fbv,
                                       o0w, o0b, o1w, o1b, out);
}

// round 17
// speedup vs baseline: 1.6146x; 1.0369x over previous
#include <cuda_runtime.h>
#include <cuda_bf16.h>
#include <cstdint>

#define TT 128
#define BB 256
#define FF 76
#define HH 64
#define GG 192   // 3*H
#define NHEAD 4
#define DFF 256
#define AH 8

// ---------------- scratch (device globals; no runtime allocation) ----------------
__device__ float g_hs[(size_t)FF * BB * TT * HH];   // [F][B][T][H]
__device__ float g_emb[(size_t)BB * FF * HH];       // [B][F][H]

// ---------------- helpers ----------------
__device__ __forceinline__ float sigmoidf_(float x) {
    return __fdividef(1.0f, 1.0f + __expf(-x));
}
__device__ __forceinline__ float tanh_ap(float x) {
    float y;
    asm("tanh.approx.f32 %0, %1;" : "=f"(y) : "f"(x));
    return y;
}
__device__ __forceinline__ unsigned long long ffma2(unsigned long long a,
                                                    unsigned long long b,
                                                    unsigned long long c) {
    unsigned long long d;
    asm("fma.rn.f32x2 %0, %1, %2, %3;" : "=l"(d) : "l"(a), "l"(b), "l"(c));
    return d;
}
__device__ __forceinline__ unsigned long long dup2(float v) {
    unsigned long long d;
    asm("mov.b64 %0, {%1, %1};" : "=l"(d) : "f"(v));
    return d;
}
__device__ __forceinline__ float2 u2f(unsigned long long u) {
    return *(float2*)&u;
}

// =====================================================================
// Kernel A: fused per-feature GRU scan + per-(f,b) time attention.
// Scan: exact R13 (FFMA2 floor). Tail: 3 barriers per batch (was 6):
// per-warp redundant q via shfl, deferred softmax normalization.
// =====================================================================
#define WT_S 194          // wT row stride (floats)
#define HT_S 34           // h row stride (floats, even)
#define XCH 32            // t-chunk
#define SMEM_A_FLOATS (64 * WT_S + 2 * 64 * HT_S + GG + 128 + 64 + 64 + XCH * 32)

__global__ void __launch_bounds__(128, 3) gru_attn_kernel(
    const float* __restrict__ x,        // (T,B,F)
    const float* __restrict__ w_ih,     // (F,3H)
    const float* __restrict__ w_hh,     // (F,3H,H)
    const float* __restrict__ b_ih,     // (F,3H)
    const float* __restrict__ b_hh,     // (F,3H)
    const float* __restrict__ att_Wt,   // (F,H,AH)
    const float* __restrict__ att_Wx,   // (F,H,AH)
    const float* __restrict__ att_rate) // (F,)
{
    extern __shared__ float sm[];
    float* wT   = sm;                          // [64][194]
    float* hbuf = wT + 64 * WT_S;              // 2 x [64][34]
    float* swih = hbuf + 2 * 64 * HT_S;        // 192 (*0.5 for first 128)
    float* sbrz = swih + GG;                   // 128
    float* sbin = sbrz + 128;                  // 64
    float* sbhn = sbin + 64;                   // 64
    float* sxc  = sbhn + 64;                   // XCH*32

    const int f  = blockIdx.y;
    const int b0 = blockIdx.x * 32;
    const int tid = threadIdx.x;
    const int tx = tid & 31, ty = tid >> 5;
    const int j0 = 2 * tx;
    const int bloc = 8 * ty;

    const float* whf = w_hh + (size_t)f * GG * HH;
    for (int idx = tid; idx < GG * HH; idx += 128) {
        const int g = idx >> 6, k = idx & 63;
        const float s = (g < 128) ? 0.5f : 1.0f;
        wT[k * WT_S + g] = whf[idx] * s;
    }
    for (int idx = tid; idx < GG; idx += 128) {
        const float s = (idx < 128) ? 0.5f : 1.0f;
        swih[idx] = w_ih[(size_t)f * GG + idx] * s;
    }
    if (tid < 128) sbrz[tid] = 0.5f * (b_ih[(size_t)f * GG + tid] + b_hh[(size_t)f * GG + tid]);
    if (tid < 64) {
        sbin[tid] = b_ih[(size_t)f * GG + 128 + tid];
        sbhn[tid] = b_hh[(size_t)f * GG + 128 + tid];
    }
    for (int idx = tid; idx < 2 * 64 * HT_S; idx += 128) hbuf[idx] = 0.0f;
    __syncthreads();

    {
        const float wir0 = swih[j0],       wir1 = swih[j0 + 1];
        const float wiz0 = swih[64 + j0],  wiz1 = swih[64 + j0 + 1];
        const float win0 = swih[128 + j0], win1 = swih[128 + j0 + 1];
        const float br0 = sbrz[j0],      br1 = sbrz[j0 + 1];
        const float bz0 = sbrz[64 + j0], bz1 = sbrz[64 + j0 + 1];
        const float bn0 = sbin[j0],      bn1 = sbin[j0 + 1];
        const float bh0 = sbhn[j0],      bh1 = sbhn[j0 + 1];

        float2 hp[2][4];
        #pragma unroll
        for (int jj = 0; jj < 2; ++jj)
            #pragma unroll
            for (int p = 0; p < 4; ++p) hp[jj][p] = make_float2(0.f, 0.f);

        const size_t gbase0 = ((size_t)f * BB + b0 + bloc) * TT * HH + j0;

        for (int tc = 0; tc < TT / XCH; ++tc) {
            for (int idx = tid; idx < XCH * 32; idx += 128) {
                const int tt = idx >> 5, bb = idx & 31;
                sxc[idx] = x[(size_t)(tc * XCH + tt) * BB * FF + (size_t)(b0 + bb) * FF + f];
            }
            __syncthreads();

            for (int tl = 0; tl < XCH; ++tl) {
                const int t = tc * XCH + tl;
                const float* hc = hbuf + (t & 1) * 64 * HT_S;
                float* hn = hbuf + ((t & 1) ^ 1) * 64 * HT_S;

                unsigned long long accR[2][4], accZ[2][4], accN[2][4];
                #pragma unroll
                for (int jj = 0; jj < 2; ++jj)
                    #pragma unroll
                    for (int p = 0; p < 4; ++p) { accR[jj][p] = 0ull; accZ[jj][p] = 0ull; accN[jj][p] = 0ull; }

                #pragma unroll 4
                for (int k = 0; k < HH; ++k) {
                    const float* hrow = hc + k * HT_S + bloc;
                    unsigned long long hv[4];
                    #pragma unroll
                    for (int p = 0; p < 4; ++p) hv[p] = *(const unsigned long long*)(hrow + 2 * p);
                    const float* wrow = wT + k * WT_S + j0;
                    const float2 wr = *(const float2*)(wrow);
                    const float2 wz = *(const float2*)(wrow + 64);
                    const float2 wn = *(const float2*)(wrow + 128);
                    const unsigned long long wr0 = dup2(wr.x), wr1 = dup2(wr.y);
                    const unsigned long long wz0 = dup2(wz.x), wz1 = dup2(wz.y);
                    const unsigned long long wn0 = dup2(wn.x), wn1 = dup2(wn.y);
                    #pragma unroll
                    for (int p = 0; p < 4; ++p) {
                        accR[0][p] = ffma2(wr0, hv[p], accR[0][p]);
                        accR[1][p] = ffma2(wr1, hv[p], accR[1][p]);
                        accZ[0][p] = ffma2(wz0, hv[p], accZ[0][p]);
                        accZ[1][p] = ffma2(wz1, hv[p], accZ[1][p]);
                        accN[0][p] = ffma2(wn0, hv[p], accN[0][p]);
                        accN[1][p] = ffma2(wn1, hv[p], accN[1][p]);
                    }
                }

                const size_t gb = gbase0 + (size_t)t * HH;
                #pragma unroll
                for (int p = 0; p < 4; ++p) {
                    const float2 xv = *(const float2*)&sxc[tl * 32 + bloc + 2 * p];
                    const float2 aR0 = u2f(accR[0][p]), aR1 = u2f(accR[1][p]);
                    const float2 aZ0 = u2f(accZ[0][p]), aZ1 = u2f(accZ[1][p]);
                    const float2 aN0 = u2f(accN[0][p]), aN1 = u2f(accN[1][p]);

                    const float r00 = fmaf(0.5f, tanh_ap(fmaf(xv.x, wir0, aR0.x + br0)), 0.5f);
                    const float r0y = fmaf(0.5f, tanh_ap(fmaf(xv.y, wir0, aR0.y + br0)), 0.5f);
                    const float z00 = fmaf(0.5f, tanh_ap(fmaf(xv.x, wiz0, aZ0.x + bz0)), 0.5f);
                    const float z0y = fmaf(0.5f, tanh_ap(fmaf(xv.y, wiz0, aZ0.y + bz0)), 0.5f);
                    const float n00 = tanh_ap(fmaf(xv.x, win0, fmaf(r00, aN0.x + bh0, bn0)));
                    const float n0y = tanh_ap(fmaf(xv.y, win0, fmaf(r0y, aN0.y + bh0, bn0)));
                    const float h00 = fmaf(z00, hp[0][p].x - n00, n00);
                    const float h0y = fmaf(z0y, hp[0][p].y - n0y, n0y);

                    const float r10 = fmaf(0.5f, tanh_ap(fmaf(xv.x, wir1, aR1.x + br1)), 0.5f);
                    const float r1y = fmaf(0.5f, tanh_ap(fmaf(xv.y, wir1, aR1.y + br1)), 0.5f);
                    const float z10 = fmaf(0.5f, tanh_ap(fmaf(xv.x, wiz1, aZ1.x + bz1)), 0.5f);
                    const float z1y = fmaf(0.5f, tanh_ap(fmaf(xv.y, wiz1, aZ1.y + bz1)), 0.5f);
                    const float n10 = tanh_ap(fmaf(xv.x, win1, fmaf(r10, aN1.x + bh1, bn1)));
                    const float n1y = tanh_ap(fmaf(xv.y, win1, fmaf(r1y, aN1.y + bh1, bn1)));
                    const float h10 = fmaf(z10, hp[1][p].x - n10, n10);
                    const float h1y = fmaf(z1y, hp[1][p].y - n1y, n1y);

                    hp[0][p] = make_float2(h00, h0y);
                    hp[1][p] = make_float2(h10, h1y);

                    *(float2*)&hn[j0 * HT_S + bloc + 2 * p] = make_float2(h00, h0y);
                    *(float2*)&hn[(j0 + 1) * HT_S + bloc + 2 * p] = make_float2(h10, h1y);
                    *(float2*)&g_hs[gb + (size_t)(2 * p) * TT * HH] = make_float2(h00, h10);
                    *(float2*)&g_hs[gb + (size_t)(2 * p + 1) * TT * HH] = make_float2(h0y, h1y);
                }
                __syncthreads();
            }
        }
    }

    // ===== fused time-attention: 3 barriers/batch, deferred normalization =====
    float* sh   = wT;                 // 128*65 floats (wT dead)
    float* sWt  = hbuf;               // 512
    float* sWx  = hbuf + 512;         // 512
    float* sa   = hbuf + 1024;        // 128 (raw ex values)
    float* red2 = hbuf + 1160;        // 4
    float* pare = hbuf + 1168;        // 128

    for (int idx = tid; idx < HH * AH; idx += 128) {
        sWt[idx] = att_Wt[(size_t)f * HH * AH + idx];
        sWx[idx] = att_Wx[(size_t)f * HH * AH + idx];
    }
    const float sr = sigmoidf_(att_rate[f]);
    __syncthreads();

    const int lane = tid & 31;

    for (int bb = 0; bb < 32; ++bb) {
        const int bg = b0 + bb;
        const float4* hsrc4 = (const float4*)(g_hs + ((size_t)(f * BB + bg)) * TT * HH);
        #pragma unroll 4
        for (int idx = tid; idx < TT * HH / 4; idx += 128) {
            float4 v = hsrc4[idx];
            const int row = idx >> 4;
            float* d = &sh[row * 65 + ((idx & 15) << 2)];
            d[0] = v.x; d[1] = v.y; d[2] = v.z; d[3] = v.w;
        }
        __syncthreads();   // (1) tile ready

        // per-warp redundant q[8] via lane-striped partials + shfl butterflies
        float qv[AH];
        {
            const float h0 = sh[(TT - 1) * 65 + lane];
            const float h1 = sh[(TT - 1) * 65 + lane + 32];
            #pragma unroll
            for (int a = 0; a < AH; ++a) {
                float pa = h0 * sWt[lane * AH + a] + h1 * sWt[(lane + 32) * AH + a];
                #pragma unroll
                for (int o = 16; o > 0; o >>= 1) pa += __shfl_xor_sync(0xffffffffu, pa, o);
                qv[a] = pa;
            }
        }

        const int t = tid;
        unsigned long long kv2[4] = {0ull, 0ull, 0ull, 0ull};
        #pragma unroll 4
        for (int j = 0; j < HH; ++j) {
            const unsigned long long hd = dup2(sh[t * 65 + j]);
            const unsigned long long* wp = (const unsigned long long*)&sWx[j * AH];
            kv2[0] = ffma2(wp[0], hd, kv2[0]);
            kv2[1] = ffma2(wp[1], hd, kv2[1]);
            kv2[2] = ffma2(wp[2], hd, kv2[2]);
            kv2[3] = ffma2(wp[3], hd, kv2[3]);
        }
        float dp = 0.f;
        #pragma unroll
        for (int c = 0; c < 4; ++c) {
            const float2 kc = u2f(kv2[c]);
            dp += qv[2 * c] * kc.x + qv[2 * c + 1] * kc.y;
        }

        const float sig = sigmoidf_(dp);
        const float decay = (float)(TT - t);
        const float denom = sr * (__logf(2.72f + (1.0f - sig)) * decay);
        const float e = fmaxf(__fdividef(sig, denom), 0.0f);
        const float ex = __expf(e);   // e in [0,~1.45]: overflow-free

        sa[t] = ex;                   // raw (unnormalized) weight
        float s = ex;
        #pragma unroll
        for (int o = 16; o > 0; o >>= 1) s += __shfl_xor_sync(0xffffffffu, s, o);
        if (lane == 0) red2[tid >> 5] = s;
        __syncthreads();   // (2) sa + partial sums ready

        const float inv_s = __fdividef(1.0f, red2[0] + red2[1] + red2[2] + red2[3]);

        const int hidx = tid & 63, part = tid >> 6;
        float acc = 0.f;
        const int t0 = part * 64;
        for (int tt2 = t0; tt2 < t0 + 64; ++tt2) acc += sa[tt2] * sh[tt2 * 65 + hidx];
        pare[tid] = acc;
        __syncthreads();   // (3) partials ready (also fences sh for next bb)
        if (tid < 64)
            g_emb[((size_t)bg * FF + f) * HH + tid] = (pare[tid] + pare[tid + 64]) * inv_s;
    }
}

// =====================================================================
// Kernel C: per-batch MHA + FFN + FinalAttention + head. (EXACT R13 — 201us)
// =====================================================================
#define BUFSZ 4864   // 76*64

__device__ __forceinline__ void gemm76s(const float* __restrict__ sIn,
                                        const float* __restrict__ sW,
                                        const float* __restrict__ gB,
                                        float* __restrict__ sOut,
                                        int tid, bool addTo, bool relu)
{
    const int j0 = (tid & 31) * 2;
    const int i0 = tid >> 5;
    float ax[10], ay[10];
    #pragma unroll
    for (int r = 0; r < 10; ++r) { ax[r] = 0.f; ay[r] = 0.f; }
    for (int k = 0; k < HH; ++k) {
        const float2 w = *(const float2*)&sW[k * 64 + j0];
        #pragma unroll
        for (int r = 0; r < 10; ++r) {
            const float s = sIn[(i0 + 8 * r) * 64 + k];
            ax[r] += s * w.x;
            ay[r] += s * w.y;
        }
    }
    float2 bj = make_float2(0.f, 0.f);
    if (gB) bj = *(const float2*)&gB[j0];
    #pragma unroll
    for (int r = 0; r < 10; ++r) {
        const int i = i0 + 8 * r;
        if (i < FF) {
            float vx = ax[r] + bj.x;
            float vy = ay[r] + bj.y;
            if (addTo) { vx += sOut[i * 64 + j0]; vy += sOut[i * 64 + j0 + 1]; }
            if (relu)  { vx = fmaxf(vx, 0.f);     vy = fmaxf(vy, 0.f); }
            sOut[i * 64 + j0] = vx;
            sOut[i * 64 + j0 + 1] = vy;
        }
    }
}

__device__ __forceinline__ void stageW(const float* __restrict__ g,
                                       float* __restrict__ s, int tid)
{
    const float4* g4 = (const float4*)g;
    float4* s4 = (float4*)s;
    for (int i = tid; i < 1024; i += 256) s4[i] = g4[i];
}

#define SMEM_C_FLOATS (4 * BUFSZ + 5888)

__global__ void __launch_bounds__(256) mix_kernel(
    const float* __restrict__ wq, const float* __restrict__ bq,
    const float* __restrict__ wk, const float* __restrict__ bk,
    const float* __restrict__ wv, const float* __restrict__ bv,
    const float* __restrict__ wo, const float* __restrict__ bo,
    const float* __restrict__ w1, const float* __restrict__ b1,
    const float* __restrict__ w2, const float* __restrict__ b2,
    const float* __restrict__ fwq, const float* __restrict__ fbq,
    const float* __restrict__ fwk, const float* __restrict__ fbk,
    const float* __restrict__ fwv, const float* __restrict__ fbv,
    const float* __restrict__ o0w, const float* __restrict__ o0b,
    const float* __restrict__ o1w, const float* __restrict__ o1b,
    float* __restrict__ out)
{
    extern __shared__ float sm[];
    float* sE = sm;
    float* sQ = sE + BUFSZ;
    float* sK = sQ + BUFSZ;
    float* sV = sK + BUFSZ;
    float* sS = sV + BUFSZ;     // 5888

    const int tid = threadIdx.x;
    const int b = blockIdx.x;
    float* rinv = sS + 5776;

    {
        const float4* esrc = (const float4*)(g_emb + (size_t)b * FF * HH);
        float4* d4 = (float4*)sE;
        for (int idx = tid; idx < FF * HH / 4; idx += 256) d4[idx] = esrc[idx];
    }
    __syncthreads();

    stageW(wq, sS, tid); __syncthreads();
    gemm76s(sE, sS, bq, sQ, tid, false, false); __syncthreads();
    stageW(wk, sS, tid); __syncthreads();
    gemm76s(sE, sS, bk, sK, tid, false, false); __syncthreads();
    stageW(wv, sS, tid); __syncthreads();
    gemm76s(sE, sS, bv, sV, tid, false, false); __syncthreads();

    for (int h = 0; h < NHEAD; ++h) {
        const int hd = h * 16;
        for (int idx = tid; idx < FF * FF; idx += 256) {
            const int i = idx / FF, jf = idx % FF;
            const float4* qp = (const float4*)&sQ[i * HH + hd];
            const float4* kp = (const float4*)&sK[jf * HH + hd];
            float acc = 0.f;
            #pragma unroll
            for (int c = 0; c < 4; ++c) {
                const float4 qv = qp[c], kv = kp[c];
                acc += qv.x * kv.x + qv.y * kv.y + qv.z * kv.z + qv.w * kv.w;
            }
            sS[idx] = __expf(acc * 0.25f);
        }
        __syncthreads();
        if (tid < FF) {
            float s = 0.f;
            for (int jf = 0; jf < FF; ++jf) s += sS[tid * FF + jf];
            rinv[tid] = __fdividef(1.0f, s);
        }
        __syncthreads();
        for (int idx = tid; idx < FF * 16; idx += 256) {
            const int i = idx / 16, d = idx % 16;
            float acc = 0.f;
            for (int jf = 0; jf < FF; ++jf) acc += sS[i * FF + jf] * sV[jf * HH + hd + d];
            sQ[i * HH + hd + d] = acc * rinv[i];
        }
        __syncthreads();
    }

    stageW(wo, sS, tid); __syncthreads();
    gemm76s(sQ, sS, bo, sE, tid, true, false); __syncthreads();

    for (int c = 0; c < 4; ++c) {
        for (int idx = tid; idx < 1024; idx += 256) {
            const int k = idx >> 4, j4 = idx & 15;
            *(float4*)&sS[k * 64 + 4 * j4] = *(const float4*)&w1[k * DFF + 64 * c + 4 * j4];
        }
        {
            const float4* g4 = (const float4*)(w2 + 4096 * c);
            float4* s4 = (float4*)sK;
            for (int i = tid; i < 1024; i += 256) s4[i] = g4[i];
        }
        __syncthreads();
        gemm76s(sE, sS, b1 + 64 * c, sQ, tid, false, true);
        __syncthreads();
        gemm76s(sQ, sK, (c == 0) ? b2 : nullptr, sV, tid, c > 0, false);
        __syncthreads();
    }
    for (int idx = tid; idx < FF * HH; idx += 256) sE[idx] += sV[idx];
    __syncthreads();

    float* fqS = sS + 4608;
    float* wS  = sS + 4768;
    float* vS  = sS + 4848;
    float* uS  = sS + 4912;
    float* msS = sS + 4976;

    if (tid < HH) {
        float acc = fbq[tid];
        for (int k = 0; k < HH; ++k) acc += sE[(FF - 1) * HH + k] * fwq[k * HH + tid];
        fqS[tid] = acc;
    }
    stageW(fwk, sS, tid); __syncthreads();
    gemm76s(sE, sS, fbk, sQ, tid, false, false); __syncthreads();
    stageW(fwv, sS, tid); __syncthreads();
    gemm76s(sE, sS, fbv, sK, tid, false, false); __syncthreads();

    if (tid < FF) {
        float acc = 0.f;
        for (int j = 0; j < HH; ++j) acc += sQ[tid * HH + j] * fqS[j];
        wS[tid] = __expf(acc);
    }
    __syncthreads();
    if (tid < 32) {
        float s = wS[tid] + wS[tid + 32] + ((tid + 64 < FF) ? wS[tid + 64] : 0.f);
        #pragma unroll
        for (int o = 16; o > 0; o >>= 1) s += __shfl_xor_sync(0xffffffffu, s, o);
        if (tid == 0) msS[0] = __fdividef(1.0f, s);
    }
    __syncthreads();
    const float inv = msS[0];
    if (tid < HH) {
        float acc = 0.f;
        for (int i = 0; i < FF; ++i) acc += (wS[i] * inv) * sK[i * HH + tid];
        vS[tid] = acc;
    }
    __syncthreads();
    if (tid < HH) {
        float acc = o0b[tid];
        for (int k = 0; k < HH; ++k) acc += vS[k] * o0w[k * HH + tid];
        uS[tid] = fmaxf(acc, 0.0f);
    }
    __syncthreads();
    if (tid == 0) {
        float acc = o1b[0];
        for (int j = 0; j < HH; ++j) acc += uS[j] * o1w[j];
        out[b] = sigmoidf_(acc);
    }
}

// =====================================================================
extern "C" void kernel_launch(void* const* d_in, const int* in_sizes, int n_in,
                              void* d_out, int out_size)
{
    const float* x     = (const float*)d_in[0];
    const float* wih   = (const float*)d_in[1];
    const float* whh   = (const float*)d_in[2];
    const float* bih   = (const float*)d_in[3];
    const float* bhh   = (const float*)d_in[4];
    const float* aWt   = (const float*)d_in[5];
    const float* aWx   = (const float*)d_in[6];
    const float* arate = (const float*)d_in[7];
    const float* mwq = (const float*)d_in[8],  *mbq = (const float*)d_in[9];
    const float* mwk = (const float*)d_in[10], *mbk = (const float*)d_in[11];
    const float* mwv = (const float*)d_in[12], *mbv = (const float*)d_in[13];
    const float* mwo = (const float*)d_in[14], *mbo = (const float*)d_in[15];
    const float* fw1 = (const float*)d_in[16], *fb1 = (const float*)d_in[17];
    const float* fw2 = (const float*)d_in[18], *fb2 = (const float*)d_in[19];
    const float* fwq = (const float*)d_in[20], *fbq = (const float*)d_in[21];
    const float* fwk = (const float*)d_in[22], *fbk = (const float*)d_in[23];
    const float* fwv = (const float*)d_in[24], *fbv = (const float*)d_in[25];
    const float* o0w = (const float*)d_in[26], *o0b = (const float*)d_in[27];
    const float* o1w = (const float*)d_in[28], *o1b = (const float*)d_in[29];
    float* out = (float*)d_out;

    const int smemA = SMEM_A_FLOATS * 4;
    const int smemC = SMEM_C_FLOATS * 4;
    cudaFuncSetAttribute(gru_attn_kernel, cudaFuncAttributeMaxDynamicSharedMemorySize, smemA);
    cudaFuncSetAttribute(mix_kernel, cudaFuncAttributeMaxDynamicSharedMemorySize, smemC);

    gru_attn_kernel<<<dim3(8, FF), 128, smemA>>>(x, wih, whh, bih, bhh, aWt, aWx, arate);
    mix_kernel<<<BB, 256, smemC>>>(mwq, mbq, mwk, mbk, mwv, mbv, mwo, mbo,
                                   fw1, fb1, fw2, fb2,
                                   fwq, fbq, fwk, fbk, fwv, fbv,
                                   o0w, o0b, o1w, o1b, out);
}